// round 1
// baseline (speedup 1.0000x reference)
#include <cuda_runtime.h>

// ---------------------------------------------------------------------------
// MyRNN: 2-layer tanh RNN, B=4096, T=512, H=32, input dim 1, + Linear(32->1).
//
// Strategy:
//   - lane j = hidden unit j; one warp = 2 "batch pairs" (4 batch elements).
//   - batch pairs packed into f32x2; all matvec FMAs use fma.rn.f32x2 (2 MAC/inst).
//   - weights held in registers, pre-duplicated (w,w) for the packed multiply.
//   - per-step h vectors broadcast through warp-private shared memory via
//     16B loads (2 packed k entries / LDS.128, broadcast = conflict-free).
//   - x pre-packed by a tiny prepass kernel into per-pair float2 streams.
// ---------------------------------------------------------------------------

typedef unsigned long long u64;

#define B_TOT   4096
#define T_TOT   512
#define H_DIM   32
#define NPAIRS  (B_TOT / 2)          // 2048
#define PAIRS_PER_CTA 2
#define NCTAS   (NPAIRS / PAIRS_PER_CTA)  // 1024

// 8 MB static scratch for packed x: [pair][t] = (x[2p][t], x[2p+1][t])
__device__ float2 g_xpk[NPAIRS * T_TOT];

// ---------------- packed fp32x2 helpers ------------------------------------
__device__ __forceinline__ u64 pk2(float x, float y) {
    u64 r; asm("mov.b64 %0, {%1,%2};" : "=l"(r) : "f"(x), "f"(y)); return r;
}
__device__ __forceinline__ void upk2(u64 v, float& x, float& y) {
    asm("mov.b64 {%0,%1}, %2;" : "=f"(x), "=f"(y) : "l"(v));
}
__device__ __forceinline__ u64 ffma2(u64 a, u64 b, u64 c) {
    u64 d; asm("fma.rn.f32x2 %0, %1, %2, %3;" : "=l"(d) : "l"(a), "l"(b), "l"(c));
    return d;
}

__device__ __forceinline__ float tanh_fast(float x) {
    // tanh(x) = (e^{2x}-1)/(e^{2x}+1); MUFU ex2 + MUFU rcp, ~1e-6 rel err.
    x = fminf(fmaxf(x, -15.0f), 15.0f);
    float e = __expf(2.0f * x);
    return __fdividef(e - 1.0f, e + 1.0f);
}
__device__ __forceinline__ u64 tanh2(u64 v) {
    float x, y; upk2(v, x, y);
    return pk2(tanh_fast(x), tanh_fast(y));
}

// ---------------- prepass: pack x into per-pair float2 streams -------------
__global__ void pack_x_kernel(const float* __restrict__ x) {
    int i = blockIdx.x * blockDim.x + threadIdx.x;   // 0 .. NPAIRS*T_TOT-1
    int p = i >> 9;          // pair
    int t = i & 511;         // time
    g_xpk[i] = make_float2(x[(2 * p) * T_TOT + t], x[(2 * p + 1) * T_TOT + t]);
}

// ---------------- main persistent-per-warp RNN kernel ----------------------
__global__ void __launch_bounds__(32)
rnn_kernel(const float* __restrict__ hstate,
           const float* __restrict__ Wih0, const float* __restrict__ Whh0,
           const float* __restrict__ bih0, const float* __restrict__ bhh0,
           const float* __restrict__ Wih1, const float* __restrict__ Whh1,
           const float* __restrict__ bih1, const float* __restrict__ bhh1,
           const float* __restrict__ Wfc,  const float* __restrict__ bfc,
           float* __restrict__ out)
{
    __shared__ __align__(16) u64 H0[PAIRS_PER_CTA][H_DIM];
    __shared__ __align__(16) u64 H1[PAIRS_PER_CTA][H_DIM];

    const int j  = threadIdx.x;      // hidden unit
    const int c  = blockIdx.x;       // 0..NCTAS-1; pairs 2c, 2c+1; batches 4c..4c+3
    const int p0 = 2 * c;

    // ---- weights (duplicated pairs) into registers ----
    u64 whh0[H_DIM], wih1[H_DIM], whh1[H_DIM];
#pragma unroll
    for (int k = 0; k < H_DIM; k++) { float w = Whh0[j * H_DIM + k]; whh0[k] = pk2(w, w); }
#pragma unroll
    for (int k = 0; k < H_DIM; k++) { float w = Wih1[j * H_DIM + k]; wih1[k] = pk2(w, w); }
#pragma unroll
    for (int k = 0; k < H_DIM; k++) { float w = Whh1[j * H_DIM + k]; whh1[k] = pk2(w, w); }

    const float wi0s = Wih0[j];
    const u64 wih0d = pk2(wi0s, wi0s);
    const float b0s = bih0[j] + bhh0[j];
    const float b1s = bih1[j] + bhh1[j];
    const u64 b0 = pk2(b0s, b0s);
    const u64 b1 = pk2(b1s, b1s);

    // ---- initial state ----
    u64 h0c[PAIRS_PER_CTA], h1c[PAIRS_PER_CTA];
#pragma unroll
    for (int pp = 0; pp < PAIRS_PER_CTA; pp++) {
        int bA = (p0 + pp) * 2, bB = bA + 1;
        h0c[pp] = pk2(hstate[bA * H_DIM + j], hstate[bB * H_DIM + j]);
        h1c[pp] = pk2(hstate[B_TOT * H_DIM + bA * H_DIM + j],
                      hstate[B_TOT * H_DIM + bB * H_DIM + j]);
        H0[pp][j] = h0c[pp];
        H1[pp][j] = h1c[pp];
    }
    __syncwarp();

    const u64* xq0 = reinterpret_cast<const u64*>(g_xpk) + (size_t)p0 * T_TOT;
    const u64* xq1 = xq0 + T_TOT;

    for (int t = 0; t < T_TOT; t++) {
        u64 xa = __ldg(xq0 + t);
        u64 xb = __ldg(xq1 + t);

        // phase A: layer0 (Whh0 * h0_old + x*Wih0 + b0) and layer1 Whh1*h1_old part
        u64 a0A = ffma2(wih0d, xa, b0);
        u64 a0B = ffma2(wih0d, xb, b0);
        u64 a1A = b1, a1B = b1;
#pragma unroll
        for (int kk = 0; kk < H_DIM / 2; kk++) {
            ulonglong2 hA = *reinterpret_cast<const ulonglong2*>(&H0[0][2 * kk]);
            ulonglong2 hB = *reinterpret_cast<const ulonglong2*>(&H0[1][2 * kk]);
            ulonglong2 gA = *reinterpret_cast<const ulonglong2*>(&H1[0][2 * kk]);
            ulonglong2 gB = *reinterpret_cast<const ulonglong2*>(&H1[1][2 * kk]);
            a0A = ffma2(whh0[2 * kk],     hA.x, a0A);
            a0A = ffma2(whh0[2 * kk + 1], hA.y, a0A);
            a0B = ffma2(whh0[2 * kk],     hB.x, a0B);
            a0B = ffma2(whh0[2 * kk + 1], hB.y, a0B);
            a1A = ffma2(whh1[2 * kk],     gA.x, a1A);
            a1A = ffma2(whh1[2 * kk + 1], gA.y, a1A);
            a1B = ffma2(whh1[2 * kk],     gB.x, a1B);
            a1B = ffma2(whh1[2 * kk + 1], gB.y, a1B);
        }
        h0c[0] = tanh2(a0A);
        h0c[1] = tanh2(a0B);

        __syncwarp();                 // all lanes done reading H0_old / H1_old
        H0[0][j] = h0c[0];
        H0[1][j] = h0c[1];
        __syncwarp();                 // h0_new visible

        // phase B: layer1 Wih1 * h0_new part
#pragma unroll
        for (int kk = 0; kk < H_DIM / 2; kk++) {
            ulonglong2 hA = *reinterpret_cast<const ulonglong2*>(&H0[0][2 * kk]);
            ulonglong2 hB = *reinterpret_cast<const ulonglong2*>(&H0[1][2 * kk]);
            a1A = ffma2(wih1[2 * kk],     hA.x, a1A);
            a1A = ffma2(wih1[2 * kk + 1], hA.y, a1A);
            a1B = ffma2(wih1[2 * kk],     hB.x, a1B);
            a1B = ffma2(wih1[2 * kk + 1], hB.y, a1B);
        }
        h1c[0] = tanh2(a1A);
        h1c[1] = tanh2(a1B);

        // safe: all lanes passed sync#1, so H1_old reads are complete
        H1[0][j] = h1c[0];
        H1[1][j] = h1c[1];
        __syncwarp();                 // h1_new visible for next step
    }

    // ---- outputs: pred [B], then h_new [2][B][H] ----
    const float wfcj = Wfc[j];
    const float bf   = bfc[0];
    float* h0out = out + B_TOT;                         // layer 0 states
    float* h1out = out + B_TOT + B_TOT * H_DIM;         // layer 1 states

#pragma unroll
    for (int pp = 0; pp < PAIRS_PER_CTA; pp++) {
        int bA = (p0 + pp) * 2, bB = bA + 1;

        float h0A, h0B, h1A, h1B;
        upk2(h0c[pp], h0A, h0B);
        upk2(h1c[pp], h1A, h1B);

        h0out[bA * H_DIM + j] = h0A;
        h0out[bB * H_DIM + j] = h0B;
        h1out[bA * H_DIM + j] = h1A;
        h1out[bB * H_DIM + j] = h1B;

        float pA = h1A * wfcj;
        float pB = h1B * wfcj;
#pragma unroll
        for (int m = 16; m > 0; m >>= 1) {
            pA += __shfl_xor_sync(0xffffffffu, pA, m);
            pB += __shfl_xor_sync(0xffffffffu, pB, m);
        }
        if (j == 0) {
            out[bA] = pA + bf;
            out[bB] = pB + bf;
        }
    }
}

// ---------------------------------------------------------------------------
extern "C" void kernel_launch(void* const* d_in, const int* in_sizes, int n_in,
                              void* d_out, int out_size)
{
    const float* x      = (const float*)d_in[0];
    const float* hstate = (const float*)d_in[1];
    const float* Wih0   = (const float*)d_in[2];
    const float* Whh0   = (const float*)d_in[3];
    const float* bih0   = (const float*)d_in[4];
    const float* bhh0   = (const float*)d_in[5];
    const float* Wih1   = (const float*)d_in[6];
    const float* Whh1   = (const float*)d_in[7];
    const float* bih1   = (const float*)d_in[8];
    const float* bhh1   = (const float*)d_in[9];
    const float* Wfc    = (const float*)d_in[10];
    const float* bfc    = (const float*)d_in[11];
    float* out          = (float*)d_out;

    pack_x_kernel<<<(NPAIRS * T_TOT) / 256, 256>>>(x);
    rnn_kernel<<<NCTAS, 32>>>(hstate, Wih0, Whh0, bih0, bhh0,
                              Wih1, Whh1, bih1, bhh1, Wfc, bfc, out);
}